// round 15
// baseline (speedup 1.0000x reference)
#include <cuda_runtime.h>
#include <cuda_fp16.h>
#include <cstdint>

// ----------------------------------------------------------------------------
// Problem constants
// ----------------------------------------------------------------------------
#define B_   8192
#define T_   137
#define D_   384
#define K_   128
#define BM   128
#define NF   (B_*D_)
#define NW   (T_*K_*D_)

#define DCHUNK 64
#define NCH    (D_/DCHUNK)        // 6
#define STAGES 3

#define TILE_BYTES  16384         // 128 rows x 128B (64 fp16)
#define STAGE_BYTES (2*TILE_BYTES)                 // A, B
#define OFF_CONST   (STAGES*STAGE_BYTES)           // 98304
#define OFF_RED     (OFF_CONST + 3*128*4)
#define SMEM_TOTAL  (OFF_RED + 128*4*4)            // 101,888 B -> 2 CTAs/SM

// ----------------------------------------------------------------------------
// fp16 scratch (device globals; no allocation allowed)
// ----------------------------------------------------------------------------
__device__ __align__(16) __half g_f_h[NF];
__device__ __align__(16) __half g_w_h[NW];

// ----------------------------------------------------------------------------
// helpers
// ----------------------------------------------------------------------------
__device__ __forceinline__ uint32_t smem_u32(const void* p) {
    uint32_t a;
    asm("{ .reg .u64 t; cvta.to.shared.u64 t, %1; cvt.u32.u64 %0, t; }"
        : "=r"(a) : "l"(p));
    return a;
}
__device__ __forceinline__ void cp16(uint32_t saddr, const void* g) {
    asm volatile("cp.async.cg.shared.global [%0], [%1], 16;"
                 :: "r"(saddr), "l"(g) : "memory");
}
template <int N>
__device__ __forceinline__ void cp_wait() {
    asm volatile("cp.async.wait_group %0;" :: "n"(N) : "memory");
}
__device__ __forceinline__ void cp_commit() {
    asm volatile("cp.async.commit_group;" ::: "memory");
}
__device__ __forceinline__ void ldsm4(uint32_t* r, uint32_t addr) {
    asm volatile("ldmatrix.sync.aligned.m8n8.x4.shared.b16 {%0,%1,%2,%3}, [%4];"
                 : "=r"(r[0]), "=r"(r[1]), "=r"(r[2]), "=r"(r[3]) : "r"(addr));
}
__device__ __forceinline__ void mma_f16(float* c, const uint32_t* a,
                                        const uint32_t b0, const uint32_t b1) {
    asm volatile(
        "mma.sync.aligned.m16n8k16.row.col.f32.f16.f16.f32 "
        "{%0,%1,%2,%3}, {%4,%5,%6,%7}, {%8,%9}, {%0,%1,%2,%3};"
        : "+f"(c[0]), "+f"(c[1]), "+f"(c[2]), "+f"(c[3])
        : "r"(a[0]), "r"(a[1]), "r"(a[2]), "r"(a[3]), "r"(b0), "r"(b1));
}
__device__ __forceinline__ uint32_t swz128(uint32_t o) {
    return o ^ ((o >> 3) & 0x70);
}

// ----------------------------------------------------------------------------
// Pre-pass: f, W1 -> fp16 (round-to-nearest)
// ----------------------------------------------------------------------------
__global__ void __launch_bounds__(256)
split_kernel(const float* __restrict__ f, const float* __restrict__ w1)
{
    const size_t NF4 = NF / 4, NT = NF4 + NW / 4;
    size_t i = (size_t)blockIdx.x * blockDim.x + threadIdx.x;
    if (i >= NT) return;

    float4 v;
    uint2* dst;
    if (i < NF4) {
        v = ((const float4*)f)[i];
        dst = (uint2*)g_f_h + i;
    } else {
        size_t j = i - NF4;
        v = ((const float4*)w1)[j];
        dst = (uint2*)g_w_h + j;
    }
    __half2 h01 = __halves2half2(__float2half_rn(v.x), __float2half_rn(v.y));
    __half2 h23 = __halves2half2(__float2half_rn(v.z), __float2half_rn(v.w));
    uint2 u;
    u.x = *reinterpret_cast<uint32_t*>(&h01);
    u.y = *reinterpret_cast<uint32_t*>(&h23);
    *dst = u;
}

// ----------------------------------------------------------------------------
// Main kernel: 128x128x384 GEMM (fp16) + BN + LReLU + dot(W2).
// B-fragment ping-pong; POST-barrier kstep0 B preload (before ISSUE);
// wave-1 CTA desync; epilogue consts preloaded under the last chunks.
// ----------------------------------------------------------------------------
__global__ void __launch_bounds__(256, 2)
heads_mma_kernel(const float* __restrict__ b1,
                 const float* __restrict__ gamma,
                 const float* __restrict__ beta,
                 const float* __restrict__ rmean,
                 const float* __restrict__ rvar,
                 const float* __restrict__ W2,
                 const float* __restrict__ b2,
                 float* __restrict__ out)
{
    extern __shared__ char sm[];
    const uint32_t smem_base = smem_u32(sm);

    const int tid  = threadIdx.x;
    const int warp = tid >> 5;
    const int lane = tid & 31;
    const int wm   = warp & 1;       // M group (2 x 64 rows)
    const int wn   = warp >> 1;      // N group (4 x 32 cols)

    const int b0 = blockIdx.x * BM;
    const int t  = blockIdx.y;

    float* sc_s = (float*)(sm + OFF_CONST);
    float* cc_s = sc_s + 128;
    float* w2_s = sc_s + 256;
    float* red  = (float*)(sm + OFF_RED);     // [128][4]

    if (tid < 128) {
        const int k = t * K_ + tid;
        const float sc = gamma[k] * rsqrtf(rvar[k] + 1e-5f);
        sc_s[tid] = sc;
        cc_s[tid] = (b1[k] - rmean[k]) * sc + beta[k];
        w2_s[tid] = W2[k];
    }

    // global tile sources: [A, B], row-major D_=384 cols
    const __half* srcA = g_f_h + (size_t)b0 * D_;
    const __half* srcB = g_w_h + (size_t)t * (K_ * D_);

    // ISSUE chunk c: offsets recomputed inline (keeps register count low)
#define ISSUE(c) do {                                                        \
    const uint32_t _sb = smem_base + ((c) % STAGES) * STAGE_BYTES;           \
    _Pragma("unroll")                                                        \
    for (int q = 0; q < 4; q++) {                                            \
        const int _idx = q * 256 + tid;                                      \
        const int _row = _idx >> 3, _seg = _idx & 7;                         \
        const uint32_t _sw = swz128((uint32_t)(_row * 128 + _seg * 16));     \
        const int _go = _row * D_ + _seg * 8 + (c) * DCHUNK;                 \
        cp16(_sb + _sw, srcA + _go);                                         \
        cp16(_sb + TILE_BYTES + _sw, srcB + _go);                            \
    }                                                                        \
    cp_commit();                                                             \
} while (0)

    // prologue: fill 2 stages (third issued inside the pipeline)
    ISSUE(0); ISSUE(1);

    // Wave-1 desync: one CTA of each co-resident pair (b, b+148) spins ~1us
    // while its prefetch is in flight, breaking SM-level phase-lock. The
    // offset persists down each SM-slot chain for subsequent waves.
    {
        const int bid = blockIdx.y * (int)gridDim.x + blockIdx.x;
        if (bid >= 148 && bid < 296)
            __nanosleep(1000);
    }

    // ldmatrix address pre-computation
    const int grp = lane >> 3;        // 0..3 address group
    const int lr  = lane & 7;
    const uint32_t xorv = (uint32_t)(lr << 4);
    const uint32_t aHi  = (uint32_t)((grp >> 1) * 16);
    const uint32_t bHi  = (uint32_t)((grp & 1) * 16);
    const uint32_t aRow = (uint32_t)((wm * 64 + (grp & 1) * 8 + lr) * 128);
    const uint32_t bRow = (uint32_t)((wn * 32 + (grp >> 1) * 8 + lr) * 128);
    const uint32_t aBase = smem_base + aRow;
    const uint32_t bBase = smem_base + TILE_BYTES + bRow;

    float acc[4][4][4];
#pragma unroll
    for (int mi = 0; mi < 4; mi++)
#pragma unroll
        for (int ni = 0; ni < 4; ni++)
#pragma unroll
            for (int r = 0; r < 4; r++) acc[mi][ni][r] = 0.0f;

    uint32_t bfA[2][4], bfB[2][4];   // ping-pong B fragments

    // POST-barrier preload of chunk c's kstep0 B frags (legal: each thread's
    // cp_wait precedes the barrier; the barrier publishes all threads' copies
    // of stage c). Placed BEFORE ISSUE so its LDS latency hides under the
    // cp.async issue burst. bfA is dead at the previous chunk's end
    // (ping-pong ends on bfB), so zero register cost.
#define PRELOAD_B0(c) do {                                                   \
    const uint32_t _ofs = (uint32_t)(((c) % STAGES) * STAGE_BYTES);          \
    const uint32_t _cb0 = bHi ^ xorv;                                        \
    ldsm4(bfA[0], bBase + _ofs + _cb0);                                      \
    ldsm4(bfA[1], bBase + _ofs + 2048u + _cb0);                              \
} while (0)

    // k16 step using BFC as current B frags; prefetches next step's B into BFN
#define KSTEP_PP(stOfs, ks, BFC, BFN, PREF) do {                             \
    uint32_t af[4][4];                                                       \
    const uint32_t _ca = ((uint32_t)((ks) * 32) + aHi) ^ xorv;               \
    ldsm4(af[0], aBase + (stOfs) + _ca);                                     \
    if (PREF) {                                                              \
        const uint32_t _cbn = ((uint32_t)(((ks) + 1) * 32) + bHi) ^ xorv;    \
        ldsm4((BFN)[0], bBase + (stOfs) + _cbn);                             \
        ldsm4((BFN)[1], bBase + (stOfs) + 2048u + _cbn);                     \
    }                                                                        \
    _Pragma("unroll")                                                        \
    for (int mi = 0; mi < 4; mi++) {                                         \
        if (mi < 3)                                                          \
            ldsm4(af[mi + 1], aBase + (stOfs) + (uint32_t)((mi + 1) * 2048) + _ca); \
        _Pragma("unroll")                                                    \
        for (int ni = 0; ni < 4; ni++) {                                     \
            const int nf = ni >> 1, p = (ni & 1) * 2;                        \
            mma_f16(acc[mi][ni], af[mi], (BFC)[nf][p], (BFC)[nf][p + 1]);    \
        }                                                                    \
    }                                                                        \
} while (0)

    // chunk body WITHOUT the kstep0 B load (done by PRELOAD_B0)
#define CHUNK_BODY(c) do {                                                   \
    const uint32_t _ofs = (uint32_t)(((c) % STAGES) * STAGE_BYTES);          \
    KSTEP_PP(_ofs, 0, bfA, bfB, 1);                                          \
    KSTEP_PP(_ofs, 1, bfB, bfA, 1);                                          \
    KSTEP_PP(_ofs, 2, bfA, bfB, 1);                                          \
    KSTEP_PP(_ofs, 3, bfB, bfA, 0);                                          \
} while (0)

    // ---- pipeline: wait -> barrier -> preload kstep0 B -> issue -> body.
    // Barrier at chunk c orders reads of stage (c-1)%3 before ISSUE(c+2)
    // overwrites it, and publishes all threads' stage-c copies for PRELOAD.
    cp_wait<1>(); __syncthreads(); PRELOAD_B0(0); ISSUE(2); CHUNK_BODY(0);
    cp_wait<1>(); __syncthreads(); PRELOAD_B0(1); ISSUE(3); CHUNK_BODY(1);
    cp_wait<1>(); __syncthreads(); PRELOAD_B0(2); ISSUE(4); CHUNK_BODY(2);
    cp_wait<1>(); __syncthreads(); PRELOAD_B0(3); ISSUE(5); CHUNK_BODY(3);

    // preload epilogue constants (overlaps the remaining MMAs; race-free:
    // sc_s/cc_s/w2_s are read-only after the preamble)
    float scr[8], ccr[8], w2r[8];
#pragma unroll
    for (int ni = 0; ni < 4; ni++)
#pragma unroll
        for (int j = 0; j < 2; j++) {
            const int k = wn * 32 + ni * 8 + (lane & 3) * 2 + j;
            scr[ni * 2 + j] = sc_s[k];
            ccr[ni * 2 + j] = cc_s[k];
            w2r[ni * 2 + j] = w2_s[k];
        }
    const float bias = b2[t];

    cp_wait<0>(); __syncthreads(); PRELOAD_B0(4); CHUNK_BODY(4);
    PRELOAD_B0(5);                                CHUNK_BODY(5);

    // ------------------------- epilogue -------------------------
#pragma unroll
    for (int mi = 0; mi < 4; mi++) {
#pragma unroll
        for (int h = 0; h < 2; h++) {
            float s = 0.0f;
#pragma unroll
            for (int ni = 0; ni < 4; ni++) {
#pragma unroll
                for (int j = 0; j < 2; j++) {
                    float y = fmaf(acc[mi][ni][h * 2 + j],
                                   scr[ni * 2 + j], ccr[ni * 2 + j]);
                    y = fmaxf(y, 0.01f * y);          // LeakyReLU
                    s = fmaf(y, w2r[ni * 2 + j], s);
                }
            }
            s += __shfl_xor_sync(0xffffffffu, s, 1);
            s += __shfl_xor_sync(0xffffffffu, s, 2);
            if ((lane & 3) == 0) {
                const int row = wm * 64 + mi * 16 + h * 8 + (lane >> 2);
                red[row * 4 + wn] = s;
            }
        }
    }
    __syncthreads();

    if (tid < 128) {
        const float s = red[tid * 4 + 0] + red[tid * 4 + 1]
                      + red[tid * 4 + 2] + red[tid * 4 + 3] + bias;
        out[(size_t)(b0 + tid) * T_ + t] = s;
    }
#undef ISSUE
#undef PRELOAD_B0
#undef KSTEP_PP
#undef CHUNK_BODY
}

// ----------------------------------------------------------------------------
// launch
// ----------------------------------------------------------------------------
extern "C" void kernel_launch(void* const* d_in, const int* in_sizes, int n_in,
                              void* d_out, int out_size)
{
    const float* f     = (const float*)d_in[0];
    const float* W1    = (const float*)d_in[1];
    const float* b1    = (const float*)d_in[2];
    const float* gamma = (const float*)d_in[3];
    const float* beta  = (const float*)d_in[4];
    const float* rmean = (const float*)d_in[5];
    const float* rvar  = (const float*)d_in[6];
    const float* W2    = (const float*)d_in[7];
    const float* b2    = (const float*)d_in[8];
    float* out = (float*)d_out;

    {
        const size_t total4 = (size_t)NF / 4 + (size_t)NW / 4;
        const int blocks = (int)((total4 + 255) / 256);
        split_kernel<<<blocks, 256>>>(f, W1);
    }

    cudaFuncSetAttribute(heads_mma_kernel,
                         cudaFuncAttributeMaxDynamicSharedMemorySize, SMEM_TOTAL);
    dim3 grid(B_ / BM, T_);
    heads_mma_kernel<<<grid, 256, SMEM_TOTAL>>>(b1, gamma, beta, rmean, rvar,
                                                W2, b2, out);
}

// round 16
// speedup vs baseline: 1.0707x; 1.0707x over previous
#include <cuda_runtime.h>
#include <cuda_fp16.h>
#include <cstdint>

// ----------------------------------------------------------------------------
// Problem constants
// ----------------------------------------------------------------------------
#define B_   8192
#define T_   137
#define D_   384
#define K_   128
#define BM   128
#define NF   (B_*D_)
#define NW   (T_*K_*D_)

#define DCHUNK 64
#define NCH    (D_/DCHUNK)        // 6
#define STAGES 3

#define TILE_BYTES  16384         // 128 rows x 128B (64 fp16)
#define STAGE_BYTES (2*TILE_BYTES)                 // A, B
#define OFF_CONST   (STAGES*STAGE_BYTES)           // 98304
#define OFF_RED     (OFF_CONST + 3*128*4)
#define SMEM_TOTAL  (OFF_RED + 128*4*4)            // 101,888 B -> 2 CTAs/SM

// ----------------------------------------------------------------------------
// fp16 scratch (device globals; no allocation allowed)
// ----------------------------------------------------------------------------
__device__ __align__(16) __half g_f_h[NF];
__device__ __align__(16) __half g_w_h[NW];

// ----------------------------------------------------------------------------
// helpers
// ----------------------------------------------------------------------------
__device__ __forceinline__ uint32_t smem_u32(const void* p) {
    uint32_t a;
    asm("{ .reg .u64 t; cvta.to.shared.u64 t, %1; cvt.u32.u64 %0, t; }"
        : "=r"(a) : "l"(p));
    return a;
}
__device__ __forceinline__ void cp16(uint32_t saddr, const void* g) {
    asm volatile("cp.async.cg.shared.global [%0], [%1], 16;"
                 :: "r"(saddr), "l"(g) : "memory");
}
template <int N>
__device__ __forceinline__ void cp_wait() {
    asm volatile("cp.async.wait_group %0;" :: "n"(N) : "memory");
}
__device__ __forceinline__ void cp_commit() {
    asm volatile("cp.async.commit_group;" ::: "memory");
}
__device__ __forceinline__ void ldsm4(uint32_t* r, uint32_t addr) {
    asm volatile("ldmatrix.sync.aligned.m8n8.x4.shared.b16 {%0,%1,%2,%3}, [%4];"
                 : "=r"(r[0]), "=r"(r[1]), "=r"(r[2]), "=r"(r[3]) : "r"(addr));
}
__device__ __forceinline__ void mma_f16(float* c, const uint32_t* a,
                                        const uint32_t b0, const uint32_t b1) {
    asm volatile(
        "mma.sync.aligned.m16n8k16.row.col.f32.f16.f16.f32 "
        "{%0,%1,%2,%3}, {%4,%5,%6,%7}, {%8,%9}, {%0,%1,%2,%3};"
        : "+f"(c[0]), "+f"(c[1]), "+f"(c[2]), "+f"(c[3])
        : "r"(a[0]), "r"(a[1]), "r"(a[2]), "r"(a[3]), "r"(b0), "r"(b1));
}
__device__ __forceinline__ uint32_t swz128(uint32_t o) {
    return o ^ ((o >> 3) & 0x70);
}

// ----------------------------------------------------------------------------
// Pre-pass: f, W1 -> fp16 (round-to-nearest)
// ----------------------------------------------------------------------------
__global__ void __launch_bounds__(256)
split_kernel(const float* __restrict__ f, const float* __restrict__ w1)
{
    const size_t NF4 = NF / 4, NT = NF4 + NW / 4;
    size_t i = (size_t)blockIdx.x * blockDim.x + threadIdx.x;
    if (i >= NT) return;

    float4 v;
    uint2* dst;
    if (i < NF4) {
        v = ((const float4*)f)[i];
        dst = (uint2*)g_f_h + i;
    } else {
        size_t j = i - NF4;
        v = ((const float4*)w1)[j];
        dst = (uint2*)g_w_h + j;
    }
    __half2 h01 = __halves2half2(__float2half_rn(v.x), __float2half_rn(v.y));
    __half2 h23 = __halves2half2(__float2half_rn(v.z), __float2half_rn(v.w));
    uint2 u;
    u.x = *reinterpret_cast<uint32_t*>(&h01);
    u.y = *reinterpret_cast<uint32_t*>(&h23);
    *dst = u;
}

// ----------------------------------------------------------------------------
// Main kernel: 128x128x384 GEMM (fp16) + BN + LReLU + dot(W2).
// B-fragment register ping-pong; wave-1 co-resident CTA desync.
// ----------------------------------------------------------------------------
__global__ void __launch_bounds__(256, 2)
heads_mma_kernel(const float* __restrict__ b1,
                 const float* __restrict__ gamma,
                 const float* __restrict__ beta,
                 const float* __restrict__ rmean,
                 const float* __restrict__ rvar,
                 const float* __restrict__ W2,
                 const float* __restrict__ b2,
                 float* __restrict__ out)
{
    extern __shared__ char sm[];
    const uint32_t smem_base = smem_u32(sm);

    const int tid  = threadIdx.x;
    const int warp = tid >> 5;
    const int lane = tid & 31;
    const int wm   = warp & 1;       // M group (2 x 64 rows)
    const int wn   = warp >> 1;      // N group (4 x 32 cols)

    const int b0 = blockIdx.x * BM;
    const int t  = blockIdx.y;

    float* sc_s = (float*)(sm + OFF_CONST);
    float* cc_s = sc_s + 128;
    float* w2_s = sc_s + 256;
    float* red  = (float*)(sm + OFF_RED);     // [128][4]

    if (tid < 128) {
        const int k = t * K_ + tid;
        const float sc = gamma[k] * rsqrtf(rvar[k] + 1e-5f);
        sc_s[tid] = sc;
        cc_s[tid] = (b1[k] - rmean[k]) * sc + beta[k];
        w2_s[tid] = W2[k];
    }

    // global tile sources: [A, B], row-major D_=384 cols
    const __half* srcA = g_f_h + (size_t)b0 * D_;
    const __half* srcB = g_w_h + (size_t)t * (K_ * D_);

    // ISSUE chunk c: offsets recomputed inline (saves 8 live registers)
#define ISSUE(c) do {                                                        \
    const uint32_t _sb = smem_base + ((c) % STAGES) * STAGE_BYTES;           \
    _Pragma("unroll")                                                        \
    for (int q = 0; q < 4; q++) {                                            \
        const int _idx = q * 256 + tid;                                      \
        const int _row = _idx >> 3, _seg = _idx & 7;                         \
        const uint32_t _sw = swz128((uint32_t)(_row * 128 + _seg * 16));     \
        const int _go = _row * D_ + _seg * 8 + (c) * DCHUNK;                 \
        cp16(_sb + _sw, srcA + _go);                                         \
        cp16(_sb + TILE_BYTES + _sw, srcB + _go);                            \
    }                                                                        \
    cp_commit();                                                             \
} while (0)

    // prologue: fill 2 stages (third issued inside the pipeline)
    ISSUE(0); ISSUE(1);

    // Wave-1 desync: exactly one CTA of each co-resident pair (b, b+148)
    // spins ~1us while its prefetch is in flight, breaking the phase-lock
    // between the two CTAs sharing an SM. The offset persists down each
    // SM-slot chain for all subsequent waves (slots inherit finish times).
    {
        const int bid = blockIdx.y * (int)gridDim.x + blockIdx.x;
        if (bid >= 148 && bid < 296)
            __nanosleep(1000);
    }

    // ldmatrix address pre-computation
    const int grp = lane >> 3;        // 0..3 address group
    const int lr  = lane & 7;
    const uint32_t xorv = (uint32_t)(lr << 4);
    const uint32_t aHi  = (uint32_t)((grp >> 1) * 16);
    const uint32_t bHi  = (uint32_t)((grp & 1) * 16);
    const uint32_t aRow = (uint32_t)((wm * 64 + (grp & 1) * 8 + lr) * 128);
    const uint32_t bRow = (uint32_t)((wn * 32 + (grp >> 1) * 8 + lr) * 128);
    const uint32_t aBase = smem_base + aRow;
    const uint32_t bBase = smem_base + TILE_BYTES + bRow;

    float acc[4][4][4];
#pragma unroll
    for (int mi = 0; mi < 4; mi++)
#pragma unroll
        for (int ni = 0; ni < 4; ni++)
#pragma unroll
            for (int r = 0; r < 4; r++) acc[mi][ni][r] = 0.0f;

    uint32_t bfA[2][4], bfB[2][4];   // ping-pong B fragments

    // k16 step using BFC as current B frags; prefetches next step's B into BFN
#define KSTEP_PP(stOfs, ks, BFC, BFN, PREF) do {                             \
    uint32_t af[4][4];                                                       \
    const uint32_t _ca = ((uint32_t)((ks) * 32) + aHi) ^ xorv;               \
    ldsm4(af[0], aBase + (stOfs) + _ca);                                     \
    if (PREF) {                                                              \
        const uint32_t _cbn = ((uint32_t)(((ks) + 1) * 32) + bHi) ^ xorv;    \
        ldsm4((BFN)[0], bBase + (stOfs) + _cbn);                             \
        ldsm4((BFN)[1], bBase + (stOfs) + 2048u + _cbn);                     \
    }                                                                        \
    _Pragma("unroll")                                                        \
    for (int mi = 0; mi < 4; mi++) {                                         \
        if (mi < 3)                                                          \
            ldsm4(af[mi + 1], aBase + (stOfs) + (uint32_t)((mi + 1) * 2048) + _ca); \
        _Pragma("unroll")                                                    \
        for (int ni = 0; ni < 4; ni++) {                                     \
            const int nf = ni >> 1, p = (ni & 1) * 2;                        \
            mma_f16(acc[mi][ni], af[mi], (BFC)[nf][p], (BFC)[nf][p + 1]);    \
        }                                                                    \
    }                                                                        \
} while (0)

#define CHUNK_BODY(c) do {                                                   \
    const uint32_t _ofs = (uint32_t)(((c) % STAGES) * STAGE_BYTES);          \
    {   /* load B frags for kstep 0 into bfA */                              \
        const uint32_t _cb0 = bHi ^ xorv;                                    \
        ldsm4(bfA[0], bBase + _ofs + _cb0);                                  \
        ldsm4(bfA[1], bBase + _ofs + 2048u + _cb0);                          \
    }                                                                        \
    KSTEP_PP(_ofs, 0, bfA, bfB, 1);                                          \
    KSTEP_PP(_ofs, 1, bfB, bfA, 1);                                          \
    KSTEP_PP(_ofs, 2, bfA, bfB, 1);                                          \
    KSTEP_PP(_ofs, 3, bfB, bfA, 0);                                          \
} while (0)

    // ---- pipeline: one barrier per chunk; issue c+2 right after the barrier.
    // The barrier at chunk c orders all reads of stage (c-1)%3 before the
    // ISSUE(c+2) writes into that same stage. Tail barriers merged.
    cp_wait<1>(); __syncthreads(); ISSUE(2); CHUNK_BODY(0);
    cp_wait<1>(); __syncthreads(); ISSUE(3); CHUNK_BODY(1);
    cp_wait<1>(); __syncthreads(); ISSUE(4); CHUNK_BODY(2);
    cp_wait<1>(); __syncthreads(); ISSUE(5); CHUNK_BODY(3);

    // preload epilogue constants before the last chunks (overlaps MMAs;
    // sc_s/cc_s/w2_s are read-only after the preamble, so this is race-free)
    float scr[8], ccr[8], w2r[8];
#pragma unroll
    for (int ni = 0; ni < 4; ni++)
#pragma unroll
        for (int j = 0; j < 2; j++) {
            const int k = wn * 32 + ni * 8 + (lane & 3) * 2 + j;
            scr[ni * 2 + j] = sc_s[k];
            ccr[ni * 2 + j] = cc_s[k];
            w2r[ni * 2 + j] = w2_s[k];
        }
    const float bias = b2[t];

    cp_wait<0>(); __syncthreads();           CHUNK_BODY(4); CHUNK_BODY(5);

    // ------------------------- epilogue -------------------------
#pragma unroll
    for (int mi = 0; mi < 4; mi++) {
#pragma unroll
        for (int h = 0; h < 2; h++) {
            float s = 0.0f;
#pragma unroll
            for (int ni = 0; ni < 4; ni++) {
#pragma unroll
                for (int j = 0; j < 2; j++) {
                    float y = fmaf(acc[mi][ni][h * 2 + j],
                                   scr[ni * 2 + j], ccr[ni * 2 + j]);
                    y = fmaxf(y, 0.01f * y);          // LeakyReLU
                    s = fmaf(y, w2r[ni * 2 + j], s);
                }
            }
            s += __shfl_xor_sync(0xffffffffu, s, 1);
            s += __shfl_xor_sync(0xffffffffu, s, 2);
            if ((lane & 3) == 0) {
                const int row = wm * 64 + mi * 16 + h * 8 + (lane >> 2);
                red[row * 4 + wn] = s;
            }
        }
    }
    __syncthreads();

    if (tid < 128) {
        const float s = red[tid * 4 + 0] + red[tid * 4 + 1]
                      + red[tid * 4 + 2] + red[tid * 4 + 3] + bias;
        out[(size_t)(b0 + tid) * T_ + t] = s;
    }
#undef ISSUE
#undef KSTEP_PP
#undef CHUNK_BODY
}

// ----------------------------------------------------------------------------
// launch
// ----------------------------------------------------------------------------
extern "C" void kernel_launch(void* const* d_in, const int* in_sizes, int n_in,
                              void* d_out, int out_size)
{
    const float* f     = (const float*)d_in[0];
    const float* W1    = (const float*)d_in[1];
    const float* b1    = (const float*)d_in[2];
    const float* gamma = (const float*)d_in[3];
    const float* beta  = (const float*)d_in[4];
    const float* rmean = (const float*)d_in[5];
    const float* rvar  = (const float*)d_in[6];
    const float* W2    = (const float*)d_in[7];
    const float* b2    = (const float*)d_in[8];
    float* out = (float*)d_out;

    {
        const size_t total4 = (size_t)NF / 4 + (size_t)NW / 4;
        const int blocks = (int)((total4 + 255) / 256);
        split_kernel<<<blocks, 256>>>(f, W1);
    }

    cudaFuncSetAttribute(heads_mma_kernel,
                         cudaFuncAttributeMaxDynamicSharedMemorySize, SMEM_TOTAL);
    dim3 grid(B_ / BM, T_);
    heads_mma_kernel<<<grid, 256, SMEM_TOTAL>>>(b1, gamma, beta, rmean, rvar,
                                                W2, b2, out);
}